// round 12
// baseline (speedup 1.0000x reference)
#include <cuda_runtime.h>
#include <cuda_fp16.h>
#include <cstdint>

// Problem constants (B=4, S=2048, H=1024, E=8, TOP_K=2)
#define NE    8
#define NTOK  8192
#define HDIM  1024
#define EPSI  1e-10f

// GEMM tiling
#define BM 128
#define BN 128
#define BK 64
#define NTILES (HDIM / BN)          // 8
#define MAXMT  (NTOK * 2 / BM + NE) // 136

// SMEM: 3 stages; per stage A/B each 128 rows x 72 fp16 (144B stride)
#define ROWST 72
#define TILE_B (128 * ROWST * 2)    // 18432 bytes per sub-tile
#define ST_BYTES (2 * TILE_B)       // 36864
#define SM_A 0
#define SM_B TILE_B
#define NSTAGE 3
#define SMEM_TOTAL (NSTAGE * ST_BYTES)   // 110592 (2 CTAs/SM: 216KB <= 228KB)

// ---------------- device scratch (static, allocation-free) ----------------
__device__ int   g_counts[NE];           // zeroed at END of combine (invariant)
__device__ int   g_texp[NTOK * 2];
__device__ int   g_tslot[NTOK * 2];
__device__ float g_tcoef[NTOK * 2];

// fixed-capacity per-expert regions: row = e * NTOK + slot
__device__ __align__(16) __half X_h[(size_t)NE * NTOK * HDIM];
__device__ __align__(16) __half WT_h[(size_t)NE * HDIM * HDIM];
__device__ __align__(16) __half Y_h[(size_t)NE * NTOK * HDIM];

// ---------------- PTX helpers ----------------
__device__ __forceinline__ uint32_t smem_u32(const void* p) {
    uint32_t a;
    asm("{ .reg .u64 t; cvta.to.shared.u64 t, %1; cvt.u32.u64 %0, t; }" : "=r"(a) : "l"(p));
    return a;
}
__device__ __forceinline__ void cp16(uint32_t dst, const void* src) {
    asm volatile("cp.async.cg.shared.global [%0], [%1], 16;" :: "r"(dst), "l"(src));
}
__device__ __forceinline__ void cp16z(uint32_t dst, const void* src, uint32_t src_size) {
    asm volatile("cp.async.cg.shared.global [%0], [%1], 16, %2;"
                 :: "r"(dst), "l"(src), "r"(src_size));
}
#define CP_COMMIT() asm volatile("cp.async.commit_group;" ::: "memory")
#define CP_WAIT(n)  asm volatile("cp.async.wait_group %0;" :: "n"(n) : "memory")

__device__ __forceinline__ void ldm_x4(uint32_t* r, uint32_t addr) {
    asm volatile("ldmatrix.sync.aligned.m8n8.x4.shared.b16 {%0,%1,%2,%3}, [%4];"
                 : "=r"(r[0]), "=r"(r[1]), "=r"(r[2]), "=r"(r[3]) : "r"(addr));
}
__device__ __forceinline__ void mma_fp16(float* d, const uint32_t* a, const uint32_t* b) {
    asm volatile("mma.sync.aligned.m16n8k16.row.col.f32.f16.f16.f32 "
                 "{%0,%1,%2,%3}, {%4,%5,%6,%7}, {%8,%9}, {%0,%1,%2,%3};"
                 : "+f"(d[0]), "+f"(d[1]), "+f"(d[2]), "+f"(d[3])
                 : "r"(a[0]), "r"(a[1]), "r"(a[2]), "r"(a[3]), "r"(b[0]), "r"(b[1]));
}

// ---------------- fused prep: wtrans (blocks 0..4095) + router (4096..) ----
#define NWT 4096   // 16 kt x 32 nt x 8 e; router: NTOK/16 = 512 blocks after

__global__ void prep_kernel(const float* __restrict__ ew,
                            const float* __restrict__ tokens,
                            const float* __restrict__ rw,
                            const float* __restrict__ rb) {
    __shared__ float sw[NE * HDIM];        // 32KB; wtrans aliases first 8448B
    int tid = threadIdx.x;

    if (blockIdx.x < NWT) {
        // ---- weight transpose [E][K][N] -> [E][N][K] fp16, 64-wide K tiles
        float (*t)[33] = reinterpret_cast<float(*)[33]>(sw);
        int b = blockIdx.x;
        int kt = b & 15, nt = (b >> 4) & 31, e = b >> 9;
        int tx = tid & 31, ty = tid >> 5;  // 32 x 8
        const float* src = ew + ((size_t)e * HDIM + kt * 64) * HDIM + nt * 32;
#pragma unroll
        for (int i = 0; i < 8; i++)
            t[ty + i * 8][tx] = src[(size_t)(ty + i * 8) * HDIM + tx];
        __syncthreads();
        size_t dbase = ((size_t)e * HDIM + nt * 32) * HDIM + kt * 64;
#pragma unroll
        for (int i = 0; i < 4; i++) {
            int n = ty + i * 8;
            __half2 v = __floats2half2_rn(t[tx * 2][n], t[tx * 2 + 1][n]);
            *reinterpret_cast<__half2*>(&WT_h[dbase + (size_t)n * HDIM + tx * 2]) = v;
        }
        return;
    }

    // ---- router + fused gather: 2 tokens per warp, float4 LDS
    for (int i = tid; i < NE * HDIM; i += blockDim.x) sw[i] = rw[i];
    __syncthreads();
    const float4* sw4 = reinterpret_cast<const float4*>(sw);

    int warp = tid >> 5, lane = tid & 31;
    int token0 = (blockIdx.x - NWT) * 16 + warp * 2;   // warp handles token0, token0+1

    const float4* x0 = reinterpret_cast<const float4*>(tokens + (size_t)token0 * HDIM);
    const float4* x1 = reinterpret_cast<const float4*>(tokens + (size_t)(token0 + 1) * HDIM);

    float a0[NE], a1[NE];
#pragma unroll
    for (int e = 0; e < NE; e++) { a0[e] = 0.f; a1[e] = 0.f; }
#pragma unroll
    for (int j = 0; j < 8; j++) {
        int i4 = lane + j * 32;                        // 256 float4 per row
        float4 v0 = x0[i4], v1 = x1[i4];
#pragma unroll
        for (int e = 0; e < NE; e++) {
            float4 w = sw4[e * 256 + i4];
            a0[e] += v0.x * w.x + v0.y * w.y + v0.z * w.z + v0.w * w.w;
            a1[e] += v1.x * w.x + v1.y * w.y + v1.z * w.z + v1.w * w.w;
        }
    }
#pragma unroll
    for (int off = 16; off > 0; off >>= 1)
#pragma unroll
        for (int e = 0; e < NE; e++) {
            a0[e] += __shfl_xor_sync(0xffffffffu, a0[e], off);
            a1[e] += __shfl_xor_sync(0xffffffffu, a1[e], off);
        }

    // lane 0 finalizes token0, lane 1 finalizes token1 (accs valid in all lanes)
    int i0 = 0, i1 = 1, s0 = 0, s1 = 0;
    if (lane < 2) {
        int token = token0 + lane;
        float lg[NE];
#pragma unroll
        for (int e = 0; e < NE; e++) lg[e] = (lane == 0 ? a0[e] : a1[e]) + rb[e];
        float mx = lg[0];
#pragma unroll
        for (int e = 1; e < NE; e++) mx = fmaxf(mx, lg[e]);
        float p[NE], Z = 0.f;
#pragma unroll
        for (int e = 0; e < NE; e++) { p[e] = expf(lg[e] - mx); Z += p[e]; }
#pragma unroll
        for (int e = 0; e < NE; e++) p[e] /= Z;

        i0 = 0;
#pragma unroll
        for (int e = 1; e < NE; e++) if (p[e] > p[i0]) i0 = e;
        i1 = (i0 == 0) ? 1 : 0;
#pragma unroll
        for (int e = 0; e < NE; e++) if (e != i0 && p[e] > p[i1]) i1 = e;

        float p0 = p[i0], p1 = p[i1];
        float s = p0 + p1;
        float w0 = p0 / (s + EPSI), w1 = p1 / (s + EPSI);
        float swsum = w0 + w1;
        float accw = fmaxf(swsum, EPSI);
        float scale = 1.f + swsum * EPSI;
        float c0 = w0 / accw * scale, c1 = w1 / accw * scale;

        s0 = atomicAdd(&g_counts[i0], 1);
        g_texp[token * 2 + 0] = i0; g_tslot[token * 2 + 0] = s0; g_tcoef[token * 2 + 0] = c0;
        s1 = atomicAdd(&g_counts[i1], 1);
        g_texp[token * 2 + 1] = i1; g_tslot[token * 2 + 1] = s1; g_tcoef[token * 2 + 1] = c1;
    }
    // broadcast destinations for both tokens
    int e0a = __shfl_sync(0xffffffffu, i0, 0), s0a = __shfl_sync(0xffffffffu, s0, 0);
    int e1a = __shfl_sync(0xffffffffu, i1, 0), s1a = __shfl_sync(0xffffffffu, s1, 0);
    int e0b = __shfl_sync(0xffffffffu, i0, 1), s0b = __shfl_sync(0xffffffffu, s0, 1);
    int e1b = __shfl_sync(0xffffffffu, i1, 1), s1b = __shfl_sync(0xffffffffu, s1, 1);

    size_t d0a = ((size_t)e0a * NTOK + s0a) * HDIM;
    size_t d1a = ((size_t)e1a * NTOK + s1a) * HDIM;
    size_t d0b = ((size_t)e0b * NTOK + s0b) * HDIM;
    size_t d1b = ((size_t)e1b * NTOK + s1b) * HDIM;
#pragma unroll
    for (int j = 0; j < 8; j++) {
        int idx = lane + j * 32;
        float4 v0 = x0[idx], v1 = x1[idx];
        __align__(8) __half h0[4], h1[4];
        h0[0] = __float2half_rn(v0.x); h0[1] = __float2half_rn(v0.y);
        h0[2] = __float2half_rn(v0.z); h0[3] = __float2half_rn(v0.w);
        h1[0] = __float2half_rn(v1.x); h1[1] = __float2half_rn(v1.y);
        h1[2] = __float2half_rn(v1.z); h1[3] = __float2half_rn(v1.w);
        uint2 p0 = *reinterpret_cast<const uint2*>(h0);
        uint2 p1 = *reinterpret_cast<const uint2*>(h1);
        *reinterpret_cast<uint2*>(&X_h[d0a + idx * 4]) = p0;
        *reinterpret_cast<uint2*>(&X_h[d1a + idx * 4]) = p0;
        *reinterpret_cast<uint2*>(&X_h[d0b + idx * 4]) = p1;
        *reinterpret_cast<uint2*>(&X_h[d1b + idx * 4]) = p1;
    }
}

// ---------------- HMMA grouped GEMM: Y_h[e*NTOK+slot, :] = X @ W_e^T --------
// 128x128 tile, 8 warps (2x4), warp tile 64x32, fp16 single pass,
// BK=64 / 3-stage eager cp.async pipeline (16 iters).
__global__ void __launch_bounds__(256, 2) moe_gemm_mma() {
    extern __shared__ __align__(16) char smem[];

    int bid = blockIdx.x;
    int e = -1, cnt = 0;
#pragma unroll
    for (int ee = 0; ee < NE; ee++) {
        int c = g_counts[ee];
        int t = ((c + BM - 1) / BM) * NTILES;
        if (e < 0) {
            if (bid < t) { e = ee; cnt = c; }
            else bid -= t;
        }
    }
    if (e < 0) return;
    int nt = bid & (NTILES - 1);
    int mt = bid / NTILES;
    int row_base = mt * BM;
    int col_base = nt * BN;

    uint32_t sb = smem_u32(smem);
    int tid = threadIdx.x, wid = tid >> 5, lane = tid & 31;
    int wm = wid >> 2, wn = wid & 3;
    int g = lane >> 2, tg = lane & 3;

    const size_t abase = (size_t)e * NTOK * HDIM;
    const size_t wbase = ((size_t)e * HDIM + col_base) * HDIM;
    int cntrel = cnt - row_base;

    auto load_stage = [&](int c, int s) {
        uint32_t st = sb + s * ST_BYTES;
        int k0 = c * BK;
        int c16 = (tid & 7) << 4;
        int rb0 = tid >> 3;
#pragma unroll
        for (int j = 0; j < 4; j++) {
            int r = rb0 + 32 * j;
            uint32_t off = (uint32_t)(r * (ROWST * 2)) + c16;
            bool v = r < cntrel;
            cp16z(st + SM_A + off,
                  &X_h[abase + (size_t)(v ? row_base + r : 0) * HDIM + k0 + (c16 >> 1)],
                  v ? 16u : 0u);
            cp16(st + SM_B + off, &WT_h[wbase + (size_t)r * HDIM + k0 + (c16 >> 1)]);
        }
        CP_COMMIT();
    };

    float acc[4][4][4];
#pragma unroll
    for (int i = 0; i < 4; i++)
#pragma unroll
        for (int j = 0; j < 4; j++)
#pragma unroll
            for (int q = 0; q < 4; q++) acc[i][j][q] = 0.f;

    load_stage(0, 0);
    load_stage(1, 1);

    int a_row = wm * 64 + (lane & 15);
    int a_colsel = (lane >> 4) * 8;
    int b_row = wn * 32 + (lane & 7) + ((lane >> 4) << 3);
    int b_colsel = ((lane >> 3) & 1) * 8;

    const int NIT = HDIM / BK;                // 16
    int s = 0, ls = NSTAGE - 1;
    for (int c = 0; c < NIT; c++) {
        CP_WAIT(NSTAGE - 2);
        __syncthreads();
        if (c + NSTAGE - 1 < NIT) load_stage(c + NSTAGE - 1, ls);
        else CP_COMMIT();
        ls = (ls + 1 == NSTAGE) ? 0 : ls + 1;

        uint32_t st = sb + s * ST_BYTES;
        s = (s + 1 == NSTAGE) ? 0 : s + 1;
#pragma unroll
        for (int kk = 0; kk < BK; kk += 16) {
            uint32_t bh[2][4];
#pragma unroll
            for (int nb = 0; nb < 2; nb++) {
                uint32_t boff = (uint32_t)((b_row + nb * 16) * (ROWST * 2) + (kk + b_colsel) * 2);
                ldm_x4(bh[nb], st + SM_B + boff);
            }
#pragma unroll
            for (int mi = 0; mi < 4; mi++) {
                uint32_t ah[4];
                uint32_t aoff = (uint32_t)((a_row + mi * 16) * (ROWST * 2) + (kk + a_colsel) * 2);
                ldm_x4(ah, st + SM_A + aoff);
#pragma unroll
                for (int ni = 0; ni < 4; ni++)
                    mma_fp16(acc[mi][ni], ah, &bh[ni >> 1][(ni & 1) * 2]);
            }
        }
    }
    __syncthreads();

    // ---- epilogue: convert to fp16 in SMEM, coalesced uint4 stores to Y_h
    __half* s_out = reinterpret_cast<__half*>(smem);   // [128][136]
#pragma unroll
    for (int mi = 0; mi < 4; mi++)
#pragma unroll
        for (int ni = 0; ni < 4; ni++) {
            int r0 = wm * 64 + mi * 16 + g;
            int cc = wn * 32 + ni * 8 + tg * 2;
            *reinterpret_cast<__half2*>(&s_out[r0 * 136 + cc]) =
                __floats2half2_rn(acc[mi][ni][0], acc[mi][ni][1]);
            *reinterpret_cast<__half2*>(&s_out[(r0 + 8) * 136 + cc]) =
                __floats2half2_rn(acc[mi][ni][2], acc[mi][ni][3]);
        }
    __syncthreads();

#pragma unroll
    for (int i = 0; i < 8; i++) {
        int u = tid + i * 256;
        int r = u >> 4, cc = (u & 15) << 3;
        uint4 v = *reinterpret_cast<const uint4*>(&s_out[r * 136 + cc]);
        *reinterpret_cast<uint4*>(
            &Y_h[(abase + (size_t)(row_base + r) * HDIM) + col_base + cc]) = v;
    }
}

// combine: out[t] = c0 * Y_h[r0] + c1 * Y_h[r1]; block 0 re-zeroes g_counts
__global__ void combine_kernel(float* __restrict__ out) {
    int t = blockIdx.x;
    int a0 = 2 * t, a1 = 2 * t + 1;
    size_t r0 = (size_t)g_texp[a0] * NTOK + g_tslot[a0];
    size_t r1 = (size_t)g_texp[a1] * NTOK + g_tslot[a1];
    float c0 = g_tcoef[a0], c1 = g_tcoef[a1];
    int i = threadIdx.x * 8;
    uint4 p0 = *reinterpret_cast<const uint4*>(&Y_h[r0 * HDIM + i]);
    uint4 p1 = *reinterpret_cast<const uint4*>(&Y_h[r1 * HDIM + i]);
    const __half2* h0 = reinterpret_cast<const __half2*>(&p0);
    const __half2* h1 = reinterpret_cast<const __half2*>(&p1);
    float o[8];
#pragma unroll
    for (int j = 0; j < 4; j++) {
        float2 f0 = __half22float2(h0[j]);
        float2 f1 = __half22float2(h1[j]);
        o[2 * j + 0] = c0 * f0.x + c1 * f1.x;
        o[2 * j + 1] = c0 * f0.y + c1 * f1.y;
    }
    float4* dst = reinterpret_cast<float4*>(&out[(size_t)t * HDIM + i]);
    dst[0] = make_float4(o[0], o[1], o[2], o[3]);
    dst[1] = make_float4(o[4], o[5], o[6], o[7]);

    if (blockIdx.x == 0 && threadIdx.x < NE) g_counts[threadIdx.x] = 0;
}

// ---------------- launch ----------------
extern "C" void kernel_launch(void* const* d_in, const int* in_sizes, int n_in,
                              void* d_out, int out_size) {
    const float* tokens = (const float*)d_in[0];   // [4,2048,1024]
    const float* rw     = (const float*)d_in[1];   // [8,1024]
    const float* rb     = (const float*)d_in[2];   // [8]
    const float* ew     = (const float*)d_in[3];   // [8,1024,1024]
    float* out = (float*)d_out;

    cudaFuncSetAttribute(moe_gemm_mma, cudaFuncAttributeMaxDynamicSharedMemorySize, SMEM_TOTAL);

    prep_kernel<<<NWT + NTOK / 16, 256>>>(ew, tokens, rw, rb);
    moe_gemm_mma<<<MAXMT * NTILES, 256, SMEM_TOTAL>>>();
    combine_kernel<<<NTOK, 128>>>(out);
    (void)in_sizes; (void)n_in; (void)out_size;
}

// round 13
// speedup vs baseline: 1.0498x; 1.0498x over previous
#include <cuda_runtime.h>
#include <cuda_fp16.h>
#include <cstdint>

// Problem constants (B=4, S=2048, H=1024, E=8, TOP_K=2)
#define NE    8
#define NTOK  8192
#define HDIM  1024
#define EPSI  1e-10f

// GEMM tiling
#define BM 128
#define BN 128
#define BK 64
#define NTILES (HDIM / BN)          // 8
#define MAXMT  (NTOK * 2 / BM + NE) // 136

// SMEM: 3 stages; per stage A/B each 128 rows x 72 fp16 (144B stride)
#define ROWST 72
#define TILE_B (128 * ROWST * 2)    // 18432 bytes per sub-tile
#define ST_BYTES (2 * TILE_B)       // 36864
#define SM_A 0
#define SM_B TILE_B
#define NSTAGE 3
#define SMEM_TOTAL (NSTAGE * ST_BYTES)   // 110592 (2 CTAs/SM: 216KB <= 228KB)

// ---------------- device scratch (static, allocation-free) ----------------
__device__ int   g_counts[NE];           // zeroed at END of combine (invariant)
__device__ int   g_texp[NTOK * 2];
__device__ int   g_tslot[NTOK * 2];
__device__ float g_tcoef[NTOK * 2];

// fixed-capacity per-expert regions: row = e * NTOK + slot
__device__ __align__(16) __half X_h[(size_t)NE * NTOK * HDIM];
__device__ __align__(16) __half WT_h[(size_t)NE * HDIM * HDIM];
__device__ __align__(16) __half Y_h[(size_t)NE * NTOK * HDIM];

// ---------------- PTX helpers ----------------
__device__ __forceinline__ uint32_t smem_u32(const void* p) {
    uint32_t a;
    asm("{ .reg .u64 t; cvta.to.shared.u64 t, %1; cvt.u32.u64 %0, t; }" : "=r"(a) : "l"(p));
    return a;
}
__device__ __forceinline__ void cp16(uint32_t dst, const void* src) {
    asm volatile("cp.async.cg.shared.global [%0], [%1], 16;" :: "r"(dst), "l"(src));
}
__device__ __forceinline__ void cp16z(uint32_t dst, const void* src, uint32_t src_size) {
    asm volatile("cp.async.cg.shared.global [%0], [%1], 16, %2;"
                 :: "r"(dst), "l"(src), "r"(src_size));
}
#define CP_COMMIT() asm volatile("cp.async.commit_group;" ::: "memory")
#define CP_WAIT(n)  asm volatile("cp.async.wait_group %0;" :: "n"(n) : "memory")

__device__ __forceinline__ void ldm_x4(uint32_t* r, uint32_t addr) {
    asm volatile("ldmatrix.sync.aligned.m8n8.x4.shared.b16 {%0,%1,%2,%3}, [%4];"
                 : "=r"(r[0]), "=r"(r[1]), "=r"(r[2]), "=r"(r[3]) : "r"(addr));
}
__device__ __forceinline__ void mma_fp16(float* d, const uint32_t* a, const uint32_t* b) {
    asm volatile("mma.sync.aligned.m16n8k16.row.col.f32.f16.f16.f32 "
                 "{%0,%1,%2,%3}, {%4,%5,%6,%7}, {%8,%9}, {%0,%1,%2,%3};"
                 : "+f"(d[0]), "+f"(d[1]), "+f"(d[2]), "+f"(d[3])
                 : "r"(a[0]), "r"(a[1]), "r"(a[2]), "r"(a[3]), "r"(b[0]), "r"(b[1]));
}

// ---------------- kernels ----------------
// weight transpose [E][K][N] -> [E][N][K] fp16, 64-wide K tiles.
// Small footprint: 8.5KB smem, low regs -> high occupancy.
__global__ void wtrans_kernel(const float* __restrict__ ew) {
    __shared__ float t[64][33];
    int kt = blockIdx.x, nt = blockIdx.y, e = blockIdx.z;   // 16 x 32 x 8
    int tx = threadIdx.x, ty = threadIdx.y;                 // 32 x 8
    if (e == 0 && kt == 0 && nt == 0 && ty == 0 && tx < NE) g_counts[tx] = 0;
    const float* src = ew + ((size_t)e * HDIM + kt * 64) * HDIM + nt * 32;
#pragma unroll
    for (int i = 0; i < 8; i++)
        t[ty + i * 8][tx] = src[(size_t)(ty + i * 8) * HDIM + tx];
    __syncthreads();
    size_t dbase = ((size_t)e * HDIM + nt * 32) * HDIM + kt * 64;
#pragma unroll
    for (int i = 0; i < 4; i++) {
        int n = ty + i * 8;
        __half2 v = __floats2half2_rn(t[tx * 2][n], t[tx * 2 + 1][n]);
        *reinterpret_cast<__half2*>(&WT_h[dbase + (size_t)n * HDIM + tx * 2]) = v;
    }
}

// router + fused gather: 1 token/warp, float4 LDS inner loop (low regs).
__global__ void __launch_bounds__(256) router_kernel(const float* __restrict__ tokens,
                                                     const float* __restrict__ rw,
                                                     const float* __restrict__ rb) {
    __shared__ float sw[NE * HDIM];        // 32KB
    int tid = threadIdx.x;
    for (int i = tid; i < NE * HDIM; i += blockDim.x) sw[i] = rw[i];
    __syncthreads();
    const float4* sw4 = reinterpret_cast<const float4*>(sw);

    int warp = tid >> 5, lane = tid & 31;
    int token = blockIdx.x * 8 + warp;

    const float4* x4 = reinterpret_cast<const float4*>(tokens + (size_t)token * HDIM);

    float acc[NE];
#pragma unroll
    for (int e = 0; e < NE; e++) acc[e] = 0.f;
#pragma unroll
    for (int j = 0; j < 8; j++) {
        int i4 = lane + j * 32;                        // 256 float4 per row
        float4 v = x4[i4];
#pragma unroll
        for (int e = 0; e < NE; e++) {
            float4 w = sw4[e * 256 + i4];
            acc[e] += v.x * w.x + v.y * w.y + v.z * w.z + v.w * w.w;
        }
    }
#pragma unroll
    for (int off = 16; off > 0; off >>= 1)
#pragma unroll
        for (int e = 0; e < NE; e++)
            acc[e] += __shfl_xor_sync(0xffffffffu, acc[e], off);

    int i0 = 0, i1 = 1, s0 = 0, s1 = 0;
    if (lane == 0) {
        float lg[NE];
#pragma unroll
        for (int e = 0; e < NE; e++) lg[e] = acc[e] + rb[e];
        float mx = lg[0];
#pragma unroll
        for (int e = 1; e < NE; e++) mx = fmaxf(mx, lg[e]);
        float p[NE], Z = 0.f;
#pragma unroll
        for (int e = 0; e < NE; e++) { p[e] = expf(lg[e] - mx); Z += p[e]; }
#pragma unroll
        for (int e = 0; e < NE; e++) p[e] /= Z;

        i0 = 0;
#pragma unroll
        for (int e = 1; e < NE; e++) if (p[e] > p[i0]) i0 = e;
        i1 = (i0 == 0) ? 1 : 0;
#pragma unroll
        for (int e = 0; e < NE; e++) if (e != i0 && p[e] > p[i1]) i1 = e;

        float p0 = p[i0], p1 = p[i1];
        float s = p0 + p1;
        float w0 = p0 / (s + EPSI), w1 = p1 / (s + EPSI);
        float swsum = w0 + w1;
        float accw = fmaxf(swsum, EPSI);
        float scale = 1.f + swsum * EPSI;
        float c0 = w0 / accw * scale, c1 = w1 / accw * scale;

        s0 = atomicAdd(&g_counts[i0], 1);
        g_texp[token * 2 + 0] = i0; g_tslot[token * 2 + 0] = s0; g_tcoef[token * 2 + 0] = c0;
        s1 = atomicAdd(&g_counts[i1], 1);
        g_texp[token * 2 + 1] = i1; g_tslot[token * 2 + 1] = s1; g_tcoef[token * 2 + 1] = c1;
    }
    i0 = __shfl_sync(0xffffffffu, i0, 0); s0 = __shfl_sync(0xffffffffu, s0, 0);
    i1 = __shfl_sync(0xffffffffu, i1, 0); s1 = __shfl_sync(0xffffffffu, s1, 0);

    // fused gather: convert token row to fp16 once, write to both expert rows
    size_t d0 = ((size_t)i0 * NTOK + s0) * HDIM;
    size_t d1 = ((size_t)i1 * NTOK + s1) * HDIM;
#pragma unroll
    for (int j = 0; j < 8; j++) {
        int idx = lane + j * 32;
        float4 v = x4[idx];                            // L1-hot re-read
        __align__(8) __half h[4];
        h[0] = __float2half_rn(v.x); h[1] = __float2half_rn(v.y);
        h[2] = __float2half_rn(v.z); h[3] = __float2half_rn(v.w);
        uint2 pk = *reinterpret_cast<const uint2*>(h);
        *reinterpret_cast<uint2*>(&X_h[d0 + idx * 4]) = pk;
        *reinterpret_cast<uint2*>(&X_h[d1 + idx * 4]) = pk;
    }
}

// ---------------- HMMA grouped GEMM: Y_h[e*NTOK+slot, :] = X @ W_e^T --------
// 128x128 tile, 8 warps (2x4), warp tile 64x32, fp16 single pass,
// BK=64 / 3-stage eager cp.async pipeline (16 iters).
__global__ void __launch_bounds__(256, 2) moe_gemm_mma() {
    extern __shared__ __align__(16) char smem[];

    int bid = blockIdx.x;
    int e = -1, cnt = 0;
#pragma unroll
    for (int ee = 0; ee < NE; ee++) {
        int c = g_counts[ee];
        int t = ((c + BM - 1) / BM) * NTILES;
        if (e < 0) {
            if (bid < t) { e = ee; cnt = c; }
            else bid -= t;
        }
    }
    if (e < 0) return;
    int nt = bid & (NTILES - 1);
    int mt = bid / NTILES;
    int row_base = mt * BM;
    int col_base = nt * BN;

    uint32_t sb = smem_u32(smem);
    int tid = threadIdx.x, wid = tid >> 5, lane = tid & 31;
    int wm = wid >> 2, wn = wid & 3;
    int g = lane >> 2, tg = lane & 3;

    const size_t abase = (size_t)e * NTOK * HDIM;
    const size_t wbase = ((size_t)e * HDIM + col_base) * HDIM;
    int cntrel = cnt - row_base;

    auto load_stage = [&](int c, int s) {
        uint32_t st = sb + s * ST_BYTES;
        int k0 = c * BK;
        int c16 = (tid & 7) << 4;
        int rb0 = tid >> 3;
#pragma unroll
        for (int j = 0; j < 4; j++) {
            int r = rb0 + 32 * j;
            uint32_t off = (uint32_t)(r * (ROWST * 2)) + c16;
            bool v = r < cntrel;
            cp16z(st + SM_A + off,
                  &X_h[abase + (size_t)(v ? row_base + r : 0) * HDIM + k0 + (c16 >> 1)],
                  v ? 16u : 0u);
            cp16(st + SM_B + off, &WT_h[wbase + (size_t)r * HDIM + k0 + (c16 >> 1)]);
        }
        CP_COMMIT();
    };

    float acc[4][4][4];
#pragma unroll
    for (int i = 0; i < 4; i++)
#pragma unroll
        for (int j = 0; j < 4; j++)
#pragma unroll
            for (int q = 0; q < 4; q++) acc[i][j][q] = 0.f;

    load_stage(0, 0);
    load_stage(1, 1);

    int a_row = wm * 64 + (lane & 15);
    int a_colsel = (lane >> 4) * 8;
    int b_row = wn * 32 + (lane & 7) + ((lane >> 4) << 3);
    int b_colsel = ((lane >> 3) & 1) * 8;

    const int NIT = HDIM / BK;                // 16
    int s = 0, ls = NSTAGE - 1;
    for (int c = 0; c < NIT; c++) {
        CP_WAIT(NSTAGE - 2);
        __syncthreads();
        if (c + NSTAGE - 1 < NIT) load_stage(c + NSTAGE - 1, ls);
        else CP_COMMIT();
        ls = (ls + 1 == NSTAGE) ? 0 : ls + 1;

        uint32_t st = sb + s * ST_BYTES;
        s = (s + 1 == NSTAGE) ? 0 : s + 1;
#pragma unroll
        for (int kk = 0; kk < BK; kk += 16) {
            uint32_t bh[2][4];
#pragma unroll
            for (int nb = 0; nb < 2; nb++) {
                uint32_t boff = (uint32_t)((b_row + nb * 16) * (ROWST * 2) + (kk + b_colsel) * 2);
                ldm_x4(bh[nb], st + SM_B + boff);
            }
#pragma unroll
            for (int mi = 0; mi < 4; mi++) {
                uint32_t ah[4];
                uint32_t aoff = (uint32_t)((a_row + mi * 16) * (ROWST * 2) + (kk + a_colsel) * 2);
                ldm_x4(ah, st + SM_A + aoff);
#pragma unroll
                for (int ni = 0; ni < 4; ni++)
                    mma_fp16(acc[mi][ni], ah, &bh[ni >> 1][(ni & 1) * 2]);
            }
        }
    }
    __syncthreads();

    // ---- epilogue: convert to fp16 in SMEM, coalesced uint4 stores to Y_h
    __half* s_out = reinterpret_cast<__half*>(smem);   // [128][136]
#pragma unroll
    for (int mi = 0; mi < 4; mi++)
#pragma unroll
        for (int ni = 0; ni < 4; ni++) {
            int r0 = wm * 64 + mi * 16 + g;
            int cc = wn * 32 + ni * 8 + tg * 2;
            *reinterpret_cast<__half2*>(&s_out[r0 * 136 + cc]) =
                __floats2half2_rn(acc[mi][ni][0], acc[mi][ni][1]);
            *reinterpret_cast<__half2*>(&s_out[(r0 + 8) * 136 + cc]) =
                __floats2half2_rn(acc[mi][ni][2], acc[mi][ni][3]);
        }
    __syncthreads();

#pragma unroll
    for (int i = 0; i < 8; i++) {
        int u = tid + i * 256;
        int r = u >> 4, cc = (u & 15) << 3;
        uint4 v = *reinterpret_cast<const uint4*>(&s_out[r * 136 + cc]);
        *reinterpret_cast<uint4*>(
            &Y_h[(abase + (size_t)(row_base + r) * HDIM) + col_base + cc]) = v;
    }
}

// combine: out[t] = c0 * Y_h[r0] + c1 * Y_h[r1]; block 0 re-zeroes g_counts
__global__ void combine_kernel(float* __restrict__ out) {
    int t = blockIdx.x;
    int a0 = 2 * t, a1 = 2 * t + 1;
    size_t r0 = (size_t)g_texp[a0] * NTOK + g_tslot[a0];
    size_t r1 = (size_t)g_texp[a1] * NTOK + g_tslot[a1];
    float c0 = g_tcoef[a0], c1 = g_tcoef[a1];
    int i = threadIdx.x * 8;
    uint4 p0 = *reinterpret_cast<const uint4*>(&Y_h[r0 * HDIM + i]);
    uint4 p1 = *reinterpret_cast<const uint4*>(&Y_h[r1 * HDIM + i]);
    const __half2* h0 = reinterpret_cast<const __half2*>(&p0);
    const __half2* h1 = reinterpret_cast<const __half2*>(&p1);
    float o[8];
#pragma unroll
    for (int j = 0; j < 4; j++) {
        float2 f0 = __half22float2(h0[j]);
        float2 f1 = __half22float2(h1[j]);
        o[2 * j + 0] = c0 * f0.x + c1 * f1.x;
        o[2 * j + 1] = c0 * f0.y + c1 * f1.y;
    }
    float4* dst = reinterpret_cast<float4*>(&out[(size_t)t * HDIM + i]);
    dst[0] = make_float4(o[0], o[1], o[2], o[3]);
    dst[1] = make_float4(o[4], o[5], o[6], o[7]);

    if (blockIdx.x == 0 && threadIdx.x < NE) g_counts[threadIdx.x] = 0;
}

// ---------------- launch ----------------
extern "C" void kernel_launch(void* const* d_in, const int* in_sizes, int n_in,
                              void* d_out, int out_size) {
    const float* tokens = (const float*)d_in[0];   // [4,2048,1024]
    const float* rw     = (const float*)d_in[1];   // [8,1024]
    const float* rb     = (const float*)d_in[2];   // [8]
    const float* ew     = (const float*)d_in[3];   // [8,1024,1024]
    float* out = (float*)d_out;

    cudaFuncSetAttribute(moe_gemm_mma, cudaFuncAttributeMaxDynamicSharedMemorySize, SMEM_TOTAL);

    wtrans_kernel<<<dim3(16, 32, 8), dim3(32, 8)>>>(ew);   // also zeroes g_counts
    router_kernel<<<NTOK / 8, 256>>>(tokens, rw, rb);      // fused gather
    moe_gemm_mma<<<MAXMT * NTILES, 256, SMEM_TOTAL>>>();
    combine_kernel<<<NTOK, 128>>>(out);
    (void)in_sizes; (void)n_in; (void)out_size;
}

// round 14
// speedup vs baseline: 1.0528x; 1.0028x over previous
#include <cuda_runtime.h>
#include <cuda_fp16.h>
#include <cstdint>

// Problem constants (B=4, S=2048, H=1024, E=8, TOP_K=2)
#define NE    8
#define NTOK  8192
#define HDIM  1024
#define EPSI  1e-10f

// GEMM tiling
#define BM 128
#define BN 128
#define BK 64
#define NTILES (HDIM / BN)          // 8
#define MAXMT  (NTOK * 2 / BM + NE) // 136

// SMEM: 3 stages; per stage A/B each 128 rows x 72 fp16 (144B stride)
#define ROWST 72
#define TILE_B (128 * ROWST * 2)    // 18432 bytes per sub-tile
#define ST_BYTES (2 * TILE_B)       // 36864
#define SM_A 0
#define SM_B TILE_B
#define NSTAGE 3
#define SMEM_TOTAL (NSTAGE * ST_BYTES)   // 110592 (2 CTAs/SM)

// ---------------- device scratch (static, allocation-free) ----------------
__device__ int   g_counts[NE];           // zeroed at END of combine (invariant)
__device__ int   g_tokmap[NE * NTOK];    // (e,slot) -> token (for GEMM A gather)
__device__ int   g_texp[NTOK * 2];
__device__ int   g_tslot[NTOK * 2];
__device__ float g_tcoef[NTOK * 2];

__device__ __align__(16) __half T_h[(size_t)NTOK * HDIM];        // fp16 tokens (single copy)
__device__ __align__(16) __half WT_h[(size_t)NE * HDIM * HDIM];
__device__ __align__(16) __half Y_h[(size_t)NE * NTOK * HDIM];

// ---------------- PTX helpers ----------------
__device__ __forceinline__ uint32_t smem_u32(const void* p) {
    uint32_t a;
    asm("{ .reg .u64 t; cvta.to.shared.u64 t, %1; cvt.u32.u64 %0, t; }" : "=r"(a) : "l"(p));
    return a;
}
__device__ __forceinline__ void cp16(uint32_t dst, const void* src) {
    asm volatile("cp.async.cg.shared.global [%0], [%1], 16;" :: "r"(dst), "l"(src));
}
__device__ __forceinline__ void cp16z(uint32_t dst, const void* src, uint32_t src_size) {
    asm volatile("cp.async.cg.shared.global [%0], [%1], 16, %2;"
                 :: "r"(dst), "l"(src), "r"(src_size));
}
#define CP_COMMIT() asm volatile("cp.async.commit_group;" ::: "memory")
#define CP_WAIT(n)  asm volatile("cp.async.wait_group %0;" :: "n"(n) : "memory")

__device__ __forceinline__ void ldm_x4(uint32_t* r, uint32_t addr) {
    asm volatile("ldmatrix.sync.aligned.m8n8.x4.shared.b16 {%0,%1,%2,%3}, [%4];"
                 : "=r"(r[0]), "=r"(r[1]), "=r"(r[2]), "=r"(r[3]) : "r"(addr));
}
__device__ __forceinline__ void mma_fp16(float* d, const uint32_t* a, const uint32_t* b) {
    asm volatile("mma.sync.aligned.m16n8k16.row.col.f32.f16.f16.f32 "
                 "{%0,%1,%2,%3}, {%4,%5,%6,%7}, {%8,%9}, {%0,%1,%2,%3};"
                 : "+f"(d[0]), "+f"(d[1]), "+f"(d[2]), "+f"(d[3])
                 : "r"(a[0]), "r"(a[1]), "r"(a[2]), "r"(a[3]), "r"(b[0]), "r"(b[1]));
}

// ---------------- kernels ----------------
// weight transpose [E][K][N] -> [E][N][K] fp16, 64-wide K tiles.
__global__ void wtrans_kernel(const float* __restrict__ ew) {
    __shared__ float t[64][33];
    int kt = blockIdx.x, nt = blockIdx.y, e = blockIdx.z;   // 16 x 32 x 8
    int tx = threadIdx.x, ty = threadIdx.y;                 // 32 x 8
    if (e == 0 && kt == 0 && nt == 0 && ty == 0 && tx < NE) g_counts[tx] = 0;
    const float* src = ew + ((size_t)e * HDIM + kt * 64) * HDIM + nt * 32;
#pragma unroll
    for (int i = 0; i < 8; i++)
        t[ty + i * 8][tx] = src[(size_t)(ty + i * 8) * HDIM + tx];
    __syncthreads();
    size_t dbase = ((size_t)e * HDIM + nt * 32) * HDIM + kt * 64;
#pragma unroll
    for (int i = 0; i < 4; i++) {
        int n = ty + i * 8;
        __half2 v = __floats2half2_rn(t[tx * 2][n], t[tx * 2 + 1][n]);
        *reinterpret_cast<__half2*>(&WT_h[dbase + (size_t)n * HDIM + tx * 2]) = v;
    }
}

// router: top-2 + single fp16 token copy + (e,slot)->token map
__global__ void __launch_bounds__(256) router_kernel(const float* __restrict__ tokens,
                                                     const float* __restrict__ rw,
                                                     const float* __restrict__ rb) {
    __shared__ float sw[NE * HDIM];        // 32KB
    int tid = threadIdx.x;
    for (int i = tid; i < NE * HDIM; i += blockDim.x) sw[i] = rw[i];
    __syncthreads();
    const float4* sw4 = reinterpret_cast<const float4*>(sw);

    int warp = tid >> 5, lane = tid & 31;
    int token = blockIdx.x * 8 + warp;

    const float4* x4 = reinterpret_cast<const float4*>(tokens + (size_t)token * HDIM);

    float acc[NE];
#pragma unroll
    for (int e = 0; e < NE; e++) acc[e] = 0.f;
#pragma unroll
    for (int j = 0; j < 8; j++) {
        int i4 = lane + j * 32;                        // 256 float4 per row
        float4 v = x4[i4];
#pragma unroll
        for (int e = 0; e < NE; e++) {
            float4 w = sw4[e * 256 + i4];
            acc[e] += v.x * w.x + v.y * w.y + v.z * w.z + v.w * w.w;
        }
        // convert + store this chunk to T_h (single copy, coalesced)
        __align__(8) __half h[4];
        h[0] = __float2half_rn(v.x); h[1] = __float2half_rn(v.y);
        h[2] = __float2half_rn(v.z); h[3] = __float2half_rn(v.w);
        *reinterpret_cast<uint2*>(&T_h[(size_t)token * HDIM + i4 * 4]) =
            *reinterpret_cast<const uint2*>(h);
    }
#pragma unroll
    for (int off = 16; off > 0; off >>= 1)
#pragma unroll
        for (int e = 0; e < NE; e++)
            acc[e] += __shfl_xor_sync(0xffffffffu, acc[e], off);

    if (lane == 0) {
        float lg[NE];
#pragma unroll
        for (int e = 0; e < NE; e++) lg[e] = acc[e] + rb[e];
        float mx = lg[0];
#pragma unroll
        for (int e = 1; e < NE; e++) mx = fmaxf(mx, lg[e]);
        float p[NE], Z = 0.f;
#pragma unroll
        for (int e = 0; e < NE; e++) { p[e] = expf(lg[e] - mx); Z += p[e]; }
#pragma unroll
        for (int e = 0; e < NE; e++) p[e] /= Z;

        int i0 = 0;
#pragma unroll
        for (int e = 1; e < NE; e++) if (p[e] > p[i0]) i0 = e;
        int i1 = (i0 == 0) ? 1 : 0;
#pragma unroll
        for (int e = 0; e < NE; e++) if (e != i0 && p[e] > p[i1]) i1 = e;

        float p0 = p[i0], p1 = p[i1];
        float s = p0 + p1;
        float w0 = p0 / (s + EPSI), w1 = p1 / (s + EPSI);
        float swsum = w0 + w1;
        float accw = fmaxf(swsum, EPSI);
        float scale = 1.f + swsum * EPSI;
        float c0 = w0 / accw * scale, c1 = w1 / accw * scale;

        int s0 = atomicAdd(&g_counts[i0], 1);
        g_tokmap[i0 * NTOK + s0] = token;
        g_texp[token * 2 + 0] = i0; g_tslot[token * 2 + 0] = s0; g_tcoef[token * 2 + 0] = c0;
        int s1 = atomicAdd(&g_counts[i1], 1);
        g_tokmap[i1 * NTOK + s1] = token;
        g_texp[token * 2 + 1] = i1; g_tslot[token * 2 + 1] = s1; g_tcoef[token * 2 + 1] = c1;
    }
}

// ---------------- HMMA grouped GEMM: Y_h[e*NTOK+slot, :] = T[tok] @ W_e^T ---
// 128x128 tile, 8 warps (2x4), warp tile 64x32, fp16 single pass,
// BK=64 / 3-stage eager cp.async pipeline. A-side gathers rows of T_h
// indirectly via s_tok (L2-resident, 16x reuse).
__global__ void __launch_bounds__(256, 2) moe_gemm_mma() {
    extern __shared__ __align__(16) char smem[];
    __shared__ int s_tok[BM];

    int bid = blockIdx.x;
    int e = -1, cnt = 0;
#pragma unroll
    for (int ee = 0; ee < NE; ee++) {
        int c = g_counts[ee];
        int t = ((c + BM - 1) / BM) * NTILES;
        if (e < 0) {
            if (bid < t) { e = ee; cnt = c; }
            else bid -= t;
        }
    }
    if (e < 0) return;
    int nt = bid & (NTILES - 1);
    int mt = bid / NTILES;
    int row_base = mt * BM;
    int col_base = nt * BN;

    uint32_t sb = smem_u32(smem);
    int tid = threadIdx.x, wid = tid >> 5, lane = tid & 31;
    int wm = wid >> 2, wn = wid & 3;
    int g = lane >> 2, tg = lane & 3;

    const size_t wbase = ((size_t)e * HDIM + col_base) * HDIM;
    const size_t abase = (size_t)e * NTOK * HDIM;   // Y region base

    if (tid < BM) {
        int r = row_base + tid;
        s_tok[tid] = (r < cnt) ? g_tokmap[e * NTOK + r] : -1;
    }
    __syncthreads();

    auto load_stage = [&](int c, int s) {
        uint32_t st = sb + s * ST_BYTES;
        int k0 = c * BK;
        int c16 = (tid & 7) << 4;
        int rb0 = tid >> 3;
#pragma unroll
        for (int j = 0; j < 4; j++) {
            int r = rb0 + 32 * j;
            uint32_t off = (uint32_t)(r * (ROWST * 2)) + c16;
            int tok = s_tok[r];
            bool v = tok >= 0;
            cp16z(st + SM_A + off,
                  &T_h[(size_t)(v ? tok : 0) * HDIM + k0 + (c16 >> 1)],
                  v ? 16u : 0u);
            cp16(st + SM_B + off, &WT_h[wbase + (size_t)r * HDIM + k0 + (c16 >> 1)]);
        }
        CP_COMMIT();
    };

    float acc[4][4][4];
#pragma unroll
    for (int i = 0; i < 4; i++)
#pragma unroll
        for (int j = 0; j < 4; j++)
#pragma unroll
            for (int q = 0; q < 4; q++) acc[i][j][q] = 0.f;

    load_stage(0, 0);
    load_stage(1, 1);

    int a_row = wm * 64 + (lane & 15);
    int a_colsel = (lane >> 4) * 8;
    int b_row = wn * 32 + (lane & 7) + ((lane >> 4) << 3);
    int b_colsel = ((lane >> 3) & 1) * 8;

    const int NIT = HDIM / BK;                // 16
    int s = 0, ls = NSTAGE - 1;
    for (int c = 0; c < NIT; c++) {
        CP_WAIT(NSTAGE - 2);
        __syncthreads();
        if (c + NSTAGE - 1 < NIT) load_stage(c + NSTAGE - 1, ls);
        else CP_COMMIT();
        ls = (ls + 1 == NSTAGE) ? 0 : ls + 1;

        uint32_t st = sb + s * ST_BYTES;
        s = (s + 1 == NSTAGE) ? 0 : s + 1;
#pragma unroll
        for (int kk = 0; kk < BK; kk += 16) {
            uint32_t bh[2][4];
#pragma unroll
            for (int nb = 0; nb < 2; nb++) {
                uint32_t boff = (uint32_t)((b_row + nb * 16) * (ROWST * 2) + (kk + b_colsel) * 2);
                ldm_x4(bh[nb], st + SM_B + boff);
            }
#pragma unroll
            for (int mi = 0; mi < 4; mi++) {
                uint32_t ah[4];
                uint32_t aoff = (uint32_t)((a_row + mi * 16) * (ROWST * 2) + (kk + a_colsel) * 2);
                ldm_x4(ah, st + SM_A + aoff);
#pragma unroll
                for (int ni = 0; ni < 4; ni++)
                    mma_fp16(acc[mi][ni], ah, &bh[ni >> 1][(ni & 1) * 2]);
            }
        }
    }
    __syncthreads();

    // ---- epilogue: convert to fp16 in SMEM, coalesced uint4 stores to Y_h
    __half* s_out = reinterpret_cast<__half*>(smem);   // [128][136]
#pragma unroll
    for (int mi = 0; mi < 4; mi++)
#pragma unroll
        for (int ni = 0; ni < 4; ni++) {
            int r0 = wm * 64 + mi * 16 + g;
            int cc = wn * 32 + ni * 8 + tg * 2;
            *reinterpret_cast<__half2*>(&s_out[r0 * 136 + cc]) =
                __floats2half2_rn(acc[mi][ni][0], acc[mi][ni][1]);
            *reinterpret_cast<__half2*>(&s_out[(r0 + 8) * 136 + cc]) =
                __floats2half2_rn(acc[mi][ni][2], acc[mi][ni][3]);
        }
    __syncthreads();

#pragma unroll
    for (int i = 0; i < 8; i++) {
        int u = tid + i * 256;
        int r = u >> 4, cc = (u & 15) << 3;
        uint4 v = *reinterpret_cast<const uint4*>(&s_out[r * 136 + cc]);
        *reinterpret_cast<uint4*>(
            &Y_h[(abase + (size_t)(row_base + r) * HDIM) + col_base + cc]) = v;
    }
}

// combine: out[t] = c0 * Y_h[r0] + c1 * Y_h[r1]; block 0 re-zeroes g_counts
__global__ void combine_kernel(float* __restrict__ out) {
    int t = blockIdx.x;
    int a0 = 2 * t, a1 = 2 * t + 1;
    size_t r0 = (size_t)g_texp[a0] * NTOK + g_tslot[a0];
    size_t r1 = (size_t)g_texp[a1] * NTOK + g_tslot[a1];
    float c0 = g_tcoef[a0], c1 = g_tcoef[a1];
    int i = threadIdx.x * 8;
    uint4 p0 = *reinterpret_cast<const uint4*>(&Y_h[r0 * HDIM + i]);
    uint4 p1 = *reinterpret_cast<const uint4*>(&Y_h[r1 * HDIM + i]);
    const __half2* h0 = reinterpret_cast<const __half2*>(&p0);
    const __half2* h1 = reinterpret_cast<const __half2*>(&p1);
    float o[8];
#pragma unroll
    for (int j = 0; j < 4; j++) {
        float2 f0 = __half22float2(h0[j]);
        float2 f1 = __half22float2(h1[j]);
        o[2 * j + 0] = c0 * f0.x + c1 * f1.x;
        o[2 * j + 1] = c0 * f0.y + c1 * f1.y;
    }
    float4* dst = reinterpret_cast<float4*>(&out[(size_t)t * HDIM + i]);
    dst[0] = make_float4(o[0], o[1], o[2], o[3]);
    dst[1] = make_float4(o[4], o[5], o[6], o[7]);

    if (blockIdx.x == 0 && threadIdx.x < NE) g_counts[threadIdx.x] = 0;
}

// ---------------- launch ----------------
extern "C" void kernel_launch(void* const* d_in, const int* in_sizes, int n_in,
                              void* d_out, int out_size) {
    const float* tokens = (const float*)d_in[0];   // [4,2048,1024]
    const float* rw     = (const float*)d_in[1];   // [8,1024]
    const float* rb     = (const float*)d_in[2];   // [8]
    const float* ew     = (const float*)d_in[3];   // [8,1024,1024]
    float* out = (float*)d_out;

    cudaFuncSetAttribute(moe_gemm_mma, cudaFuncAttributeMaxDynamicSharedMemorySize, SMEM_TOTAL);

    wtrans_kernel<<<dim3(16, 32, 8), dim3(32, 8)>>>(ew);   // also zeroes g_counts
    router_kernel<<<NTOK / 8, 256>>>(tokens, rw, rb);
    moe_gemm_mma<<<MAXMT * NTILES, 256, SMEM_TOTAL>>>();
    combine_kernel<<<NTOK, 128>>>(out);
    (void)in_sizes; (void)n_in; (void)out_size;
}

// round 15
// speedup vs baseline: 1.0768x; 1.0228x over previous
#include <cuda_runtime.h>
#include <cuda_fp16.h>
#include <cstdint>

// Problem constants (B=4, S=2048, H=1024, E=8, TOP_K=2)
#define NE    8
#define NTOK  8192
#define HDIM  1024
#define EPSI  1e-10f

// GEMM tiling
#define BM 128
#define BN 128
#define BK 64
#define NTILES (HDIM / BN)          // 8
#define MAXMT  (NTOK * 2 / BM + NE) // 136

// SMEM: 3 stages; per stage A/B each 128 rows x 72 fp16 (144B stride)
#define ROWST 72
#define TILE_B (128 * ROWST * 2)    // 18432 bytes per sub-tile
#define ST_BYTES (2 * TILE_B)       // 36864
#define SM_A 0
#define SM_B TILE_B
#define NSTAGE 3
#define SMEM_TOTAL (NSTAGE * ST_BYTES)   // 110592 (2 CTAs/SM)

// ---------------- device scratch (static, allocation-free) ----------------
__device__ int   g_counts[NE];           // zero-init; re-zeroed at END of combine
__device__ int   g_tokmap[NE * NTOK];    // (e,slot) -> token
__device__ int   g_texp[NTOK * 2];
__device__ int   g_tslot[NTOK * 2];
__device__ float g_tcoef[NTOK * 2];

__device__ __align__(16) __half T_h[(size_t)NTOK * HDIM];        // fp16 tokens
__device__ __align__(16) __half WT_h[(size_t)NE * HDIM * HDIM];
__device__ __align__(16) __half Y_h[(size_t)NE * NTOK * HDIM];

// ---------------- PTX helpers ----------------
__device__ __forceinline__ uint32_t smem_u32(const void* p) {
    uint32_t a;
    asm("{ .reg .u64 t; cvta.to.shared.u64 t, %1; cvt.u32.u64 %0, t; }" : "=r"(a) : "l"(p));
    return a;
}
__device__ __forceinline__ void cp16(uint32_t dst, const void* src) {
    asm volatile("cp.async.cg.shared.global [%0], [%1], 16;" :: "r"(dst), "l"(src));
}
__device__ __forceinline__ void cp16z(uint32_t dst, const void* src, uint32_t src_size) {
    asm volatile("cp.async.cg.shared.global [%0], [%1], 16, %2;"
                 :: "r"(dst), "l"(src), "r"(src_size));
}
#define CP_COMMIT() asm volatile("cp.async.commit_group;" ::: "memory")
#define CP_WAIT(n)  asm volatile("cp.async.wait_group %0;" :: "n"(n) : "memory")

__device__ __forceinline__ void ldm_x4(uint32_t* r, uint32_t addr) {
    asm volatile("ldmatrix.sync.aligned.m8n8.x4.shared.b16 {%0,%1,%2,%3}, [%4];"
                 : "=r"(r[0]), "=r"(r[1]), "=r"(r[2]), "=r"(r[3]) : "r"(addr));
}
__device__ __forceinline__ void mma_fp16(float* d, const uint32_t* a, const uint32_t* b) {
    asm volatile("mma.sync.aligned.m16n8k16.row.col.f32.f16.f16.f32 "
                 "{%0,%1,%2,%3}, {%4,%5,%6,%7}, {%8,%9}, {%0,%1,%2,%3};"
                 : "+f"(d[0]), "+f"(d[1]), "+f"(d[2]), "+f"(d[3])
                 : "r"(a[0]), "r"(a[1]), "r"(a[2]), "r"(a[3]), "r"(b[0]), "r"(b[1]));
}

// ---------------- kernels ----------------
// weight transpose [E][K][N] -> [E][N][K] fp16, 64-wide K tiles.
// NOTE: no g_counts access here — runs concurrently with router.
__global__ void wtrans_kernel(const float* __restrict__ ew) {
    __shared__ float t[64][33];
    int kt = blockIdx.x, nt = blockIdx.y, e = blockIdx.z;   // 16 x 32 x 8
    int tx = threadIdx.x, ty = threadIdx.y;                 // 32 x 8
    const float* src = ew + ((size_t)e * HDIM + kt * 64) * HDIM + nt * 32;
#pragma unroll
    for (int i = 0; i < 8; i++)
        t[ty + i * 8][tx] = src[(size_t)(ty + i * 8) * HDIM + tx];
    __syncthreads();
    size_t dbase = ((size_t)e * HDIM + nt * 32) * HDIM + kt * 64;
#pragma unroll
    for (int i = 0; i < 4; i++) {
        int n = ty + i * 8;
        __half2 v = __floats2half2_rn(t[tx * 2][n], t[tx * 2 + 1][n]);
        *reinterpret_cast<__half2*>(&WT_h[dbase + (size_t)n * HDIM + tx * 2]) = v;
    }
}

// router: top-2 + single fp16 token copy + (e,slot)->token map
__global__ void __launch_bounds__(256) router_kernel(const float* __restrict__ tokens,
                                                     const float* __restrict__ rw,
                                                     const float* __restrict__ rb) {
    __shared__ float sw[NE * HDIM];        // 32KB
    int tid = threadIdx.x;
    for (int i = tid; i < NE * HDIM; i += blockDim.x) sw[i] = rw[i];
    __syncthreads();
    const float4* sw4 = reinterpret_cast<const float4*>(sw);

    int warp = tid >> 5, lane = tid & 31;
    int token = blockIdx.x * 8 + warp;

    const float4* x4 = reinterpret_cast<const float4*>(tokens + (size_t)token * HDIM);

    float acc[NE];
#pragma unroll
    for (int e = 0; e < NE; e++) acc[e] = 0.f;
#pragma unroll
    for (int j = 0; j < 8; j++) {
        int i4 = lane + j * 32;                        // 256 float4 per row
        float4 v = x4[i4];
#pragma unroll
        for (int e = 0; e < NE; e++) {
            float4 w = sw4[e * 256 + i4];
            acc[e] += v.x * w.x + v.y * w.y + v.z * w.z + v.w * w.w;
        }
        __align__(8) __half h[4];
        h[0] = __float2half_rn(v.x); h[1] = __float2half_rn(v.y);
        h[2] = __float2half_rn(v.z); h[3] = __float2half_rn(v.w);
        *reinterpret_cast<uint2*>(&T_h[(size_t)token * HDIM + i4 * 4]) =
            *reinterpret_cast<const uint2*>(h);
    }
#pragma unroll
    for (int off = 16; off > 0; off >>= 1)
#pragma unroll
        for (int e = 0; e < NE; e++)
            acc[e] += __shfl_xor_sync(0xffffffffu, acc[e], off);

    if (lane == 0) {
        float lg[NE];
#pragma unroll
        for (int e = 0; e < NE; e++) lg[e] = acc[e] + rb[e];
        float mx = lg[0];
#pragma unroll
        for (int e = 1; e < NE; e++) mx = fmaxf(mx, lg[e]);
        float p[NE], Z = 0.f;
#pragma unroll
        for (int e = 0; e < NE; e++) { p[e] = expf(lg[e] - mx); Z += p[e]; }
#pragma unroll
        for (int e = 0; e < NE; e++) p[e] /= Z;

        int i0 = 0;
#pragma unroll
        for (int e = 1; e < NE; e++) if (p[e] > p[i0]) i0 = e;
        int i1 = (i0 == 0) ? 1 : 0;
#pragma unroll
        for (int e = 0; e < NE; e++) if (e != i0 && p[e] > p[i1]) i1 = e;

        float p0 = p[i0], p1 = p[i1];
        float s = p0 + p1;
        float w0 = p0 / (s + EPSI), w1 = p1 / (s + EPSI);
        float swsum = w0 + w1;
        float accw = fmaxf(swsum, EPSI);
        float scale = 1.f + swsum * EPSI;
        float c0 = w0 / accw * scale, c1 = w1 / accw * scale;

        int s0 = atomicAdd(&g_counts[i0], 1);
        g_tokmap[i0 * NTOK + s0] = token;
        g_texp[token * 2 + 0] = i0; g_tslot[token * 2 + 0] = s0; g_tcoef[token * 2 + 0] = c0;
        int s1 = atomicAdd(&g_counts[i1], 1);
        g_tokmap[i1 * NTOK + s1] = token;
        g_texp[token * 2 + 1] = i1; g_tslot[token * 2 + 1] = s1; g_tcoef[token * 2 + 1] = c1;
    }
}

// ---------------- HMMA grouped GEMM: Y_h[e*NTOK+slot, :] = T[tok] @ W_e^T ---
__global__ void __launch_bounds__(256, 2) moe_gemm_mma() {
    extern __shared__ __align__(16) char smem[];
    __shared__ int s_tok[BM];

    int bid = blockIdx.x;
    int e = -1, cnt = 0;
#pragma unroll
    for (int ee = 0; ee < NE; ee++) {
        int c = g_counts[ee];
        int t = ((c + BM - 1) / BM) * NTILES;
        if (e < 0) {
            if (bid < t) { e = ee; cnt = c; }
            else bid -= t;
        }
    }
    if (e < 0) return;
    int nt = bid & (NTILES - 1);
    int mt = bid / NTILES;
    int row_base = mt * BM;
    int col_base = nt * BN;

    uint32_t sb = smem_u32(smem);
    int tid = threadIdx.x, wid = tid >> 5, lane = tid & 31;
    int wm = wid >> 2, wn = wid & 3;
    int g = lane >> 2, tg = lane & 3;

    const size_t wbase = ((size_t)e * HDIM + col_base) * HDIM;
    const size_t abase = (size_t)e * NTOK * HDIM;   // Y region base

    if (tid < BM) {
        int r = row_base + tid;
        s_tok[tid] = (r < cnt) ? g_tokmap[e * NTOK + r] : -1;
    }
    __syncthreads();

    auto load_stage = [&](int c, int s) {
        uint32_t st = sb + s * ST_BYTES;
        int k0 = c * BK;
        int c16 = (tid & 7) << 4;
        int rb0 = tid >> 3;
#pragma unroll
        for (int j = 0; j < 4; j++) {
            int r = rb0 + 32 * j;
            uint32_t off = (uint32_t)(r * (ROWST * 2)) + c16;
            int tok = s_tok[r];
            bool v = tok >= 0;
            cp16z(st + SM_A + off,
                  &T_h[(size_t)(v ? tok : 0) * HDIM + k0 + (c16 >> 1)],
                  v ? 16u : 0u);
            cp16(st + SM_B + off, &WT_h[wbase + (size_t)r * HDIM + k0 + (c16 >> 1)]);
        }
        CP_COMMIT();
    };

    float acc[4][4][4];
#pragma unroll
    for (int i = 0; i < 4; i++)
#pragma unroll
        for (int j = 0; j < 4; j++)
#pragma unroll
            for (int q = 0; q < 4; q++) acc[i][j][q] = 0.f;

    load_stage(0, 0);
    load_stage(1, 1);

    int a_row = wm * 64 + (lane & 15);
    int a_colsel = (lane >> 4) * 8;
    int b_row = wn * 32 + (lane & 7) + ((lane >> 4) << 3);
    int b_colsel = ((lane >> 3) & 1) * 8;

    const int NIT = HDIM / BK;                // 16
    int s = 0, ls = NSTAGE - 1;
    for (int c = 0; c < NIT; c++) {
        CP_WAIT(NSTAGE - 2);
        __syncthreads();
        if (c + NSTAGE - 1 < NIT) load_stage(c + NSTAGE - 1, ls);
        else CP_COMMIT();
        ls = (ls + 1 == NSTAGE) ? 0 : ls + 1;

        uint32_t st = sb + s * ST_BYTES;
        s = (s + 1 == NSTAGE) ? 0 : s + 1;
#pragma unroll
        for (int kk = 0; kk < BK; kk += 16) {
            uint32_t bh[2][4];
#pragma unroll
            for (int nb = 0; nb < 2; nb++) {
                uint32_t boff = (uint32_t)((b_row + nb * 16) * (ROWST * 2) + (kk + b_colsel) * 2);
                ldm_x4(bh[nb], st + SM_B + boff);
            }
#pragma unroll
            for (int mi = 0; mi < 4; mi++) {
                uint32_t ah[4];
                uint32_t aoff = (uint32_t)((a_row + mi * 16) * (ROWST * 2) + (kk + a_colsel) * 2);
                ldm_x4(ah, st + SM_A + aoff);
#pragma unroll
                for (int ni = 0; ni < 4; ni++)
                    mma_fp16(acc[mi][ni], ah, &bh[ni >> 1][(ni & 1) * 2]);
            }
        }
    }
    __syncthreads();

    // ---- epilogue: convert to fp16 in SMEM, coalesced uint4 stores to Y_h
    __half* s_out = reinterpret_cast<__half*>(smem);   // [128][136]
#pragma unroll
    for (int mi = 0; mi < 4; mi++)
#pragma unroll
        for (int ni = 0; ni < 4; ni++) {
            int r0 = wm * 64 + mi * 16 + g;
            int cc = wn * 32 + ni * 8 + tg * 2;
            *reinterpret_cast<__half2*>(&s_out[r0 * 136 + cc]) =
                __floats2half2_rn(acc[mi][ni][0], acc[mi][ni][1]);
            *reinterpret_cast<__half2*>(&s_out[(r0 + 8) * 136 + cc]) =
                __floats2half2_rn(acc[mi][ni][2], acc[mi][ni][3]);
        }
    __syncthreads();

#pragma unroll
    for (int i = 0; i < 8; i++) {
        int u = tid + i * 256;
        int r = u >> 4, cc = (u & 15) << 3;
        uint4 v = *reinterpret_cast<const uint4*>(&s_out[r * 136 + cc]);
        *reinterpret_cast<uint4*>(
            &Y_h[(abase + (size_t)(row_base + r) * HDIM) + col_base + cc]) = v;
    }
}

// combine: out[t] = c0 * Y_h[r0] + c1 * Y_h[r1]; block 0 re-zeroes g_counts
__global__ void combine_kernel(float* __restrict__ out) {
    int t = blockIdx.x;
    int a0 = 2 * t, a1 = 2 * t + 1;
    size_t r0 = (size_t)g_texp[a0] * NTOK + g_tslot[a0];
    size_t r1 = (size_t)g_texp[a1] * NTOK + g_tslot[a1];
    float c0 = g_tcoef[a0], c1 = g_tcoef[a1];
    int i = threadIdx.x * 8;
    uint4 p0 = *reinterpret_cast<const uint4*>(&Y_h[r0 * HDIM + i]);
    uint4 p1 = *reinterpret_cast<const uint4*>(&Y_h[r1 * HDIM + i]);
    const __half2* h0 = reinterpret_cast<const __half2*>(&p0);
    const __half2* h1 = reinterpret_cast<const __half2*>(&p1);
    float o[8];
#pragma unroll
    for (int j = 0; j < 4; j++) {
        float2 f0 = __half22float2(h0[j]);
        float2 f1 = __half22float2(h1[j]);
        o[2 * j + 0] = c0 * f0.x + c1 * f1.x;
        o[2 * j + 1] = c0 * f0.y + c1 * f1.y;
    }
    float4* dst = reinterpret_cast<float4*>(&out[(size_t)t * HDIM + i]);
    dst[0] = make_float4(o[0], o[1], o[2], o[3]);
    dst[1] = make_float4(o[4], o[5], o[6], o[7]);

    if (blockIdx.x == 0 && threadIdx.x < NE) g_counts[threadIdx.x] = 0;
}

// ---------------- launch ----------------
extern "C" void kernel_launch(void* const* d_in, const int* in_sizes, int n_in,
                              void* d_out, int out_size) {
    const float* tokens = (const float*)d_in[0];   // [4,2048,1024]
    const float* rw     = (const float*)d_in[1];   // [8,1024]
    const float* rb     = (const float*)d_in[2];   // [8]
    const float* ew     = (const float*)d_in[3];   // [8,1024,1024]
    float* out = (float*)d_out;

    // one-time setup on the first (uncaptured, correctness) call — no device
    // memory allocation, only stream/event handles
    static cudaStream_t s2 = nullptr;
    static cudaEvent_t evFork = nullptr, evJoin = nullptr;
    if (s2 == nullptr) {
        cudaStreamCreateWithFlags(&s2, cudaStreamNonBlocking);
        cudaEventCreateWithFlags(&evFork, cudaEventDisableTiming);
        cudaEventCreateWithFlags(&evJoin, cudaEventDisableTiming);
        cudaFuncSetAttribute(moe_gemm_mma, cudaFuncAttributeMaxDynamicSharedMemorySize,
                             SMEM_TOTAL);
    }

    // fork: router on s2, wtrans on main stream (independent; g_counts only
    // touched by router — combine re-zeroes it at the end of every call)
    cudaEventRecord(evFork, 0);
    cudaStreamWaitEvent(s2, evFork, 0);
    router_kernel<<<NTOK / 8, 256, 0, s2>>>(tokens, rw, rb);
    wtrans_kernel<<<dim3(16, 32, 8), dim3(32, 8)>>>(ew);
    cudaEventRecord(evJoin, s2);
    cudaStreamWaitEvent(0, evJoin, 0);

    moe_gemm_mma<<<MAXMT * NTILES, 256, SMEM_TOTAL>>>();
    combine_kernel<<<NTOK, 128>>>(out);
    (void)in_sizes; (void)n_in; (void)out_size;
}